// round 3
// baseline (speedup 1.0000x reference)
#include <cuda_runtime.h>

// Rotation_agg: out[n, :] = mean_l ( cmul(feat[n,l,:], finals[l,:]) ), finals[3]=identity.
// HBM-bound stream: 1.024 GB read + 256 MB write. R1 hit 90.9% DRAM (7.2 TB/s).
// R2: streaming cache hints (__ldcs/__stcs) + 2 float4 columns per thread (MLP=8).

#define ROT_EPS 1e-12f

__global__ __launch_bounds__(256) void rotation_agg_kernel(
    const float* __restrict__ feat,
    const float* __restrict__ r_vec,
    float* __restrict__ out,
    long long total_pairs)   // N * 8 work items, each = 2 adjacent float4 columns
{
    __shared__ float2 sf[3][32];   // finals for l=0,1,2 per complex index k

    const int tid = threadIdx.x;
    if (tid < 32) {
        const int k = tid;
        float2 rn[3];
#pragma unroll
        for (int e = 0; e < 3; e++) {
            float x = r_vec[e * 64 + k * 2 + 0];
            float y = r_vec[e * 64 + k * 2 + 1];
            float nrm = sqrtf(x * x + y * y);
            float inv = 1.0f / fmaxf(nrm, ROT_EPS);
            rn[e] = make_float2(x * inv, y * inv);
        }
        float2 f2 = make_float2(rn[2].x, -rn[2].y);               // conj(rn2)
        float2 c1 = make_float2(rn[1].x, -rn[1].y);               // conj(rn1)
        float2 f1 = make_float2(f2.x * c1.x - f2.y * c1.y,
                                f2.x * c1.y + f2.y * c1.x);       // f2 * conj(rn1)
        float2 f0 = make_float2(f1.x * rn[0].x - f1.y * rn[0].y,
                                f1.x * rn[0].y + f1.y * rn[0].x); // f1 * rn0
        sf[0][k] = f0;
        sf[1][k] = f1;
        sf[2][k] = f2;
    }
    __syncthreads();

    const long long t = (long long)blockIdx.x * blockDim.x + tid;
    if (t >= total_pairs) return;

    const int n = (int)(t >> 3);
    const int p = (int)(t & 7);            // pair index -> float4 columns 2p, 2p+1

    const float4* in4 = (const float4*)feat + (long long)n * 64 + 2 * p;

    // Batch all 8 loads up front (MLP=8), evict-first streaming policy.
    float4 a0 = __ldcs(in4 + 0);
    float4 b0 = __ldcs(in4 + 1);
    float4 a1 = __ldcs(in4 + 16);
    float4 b1 = __ldcs(in4 + 17);
    float4 a2 = __ldcs(in4 + 32);
    float4 b2 = __ldcs(in4 + 33);
    float4 a3 = __ldcs(in4 + 48);
    float4 b3 = __ldcs(in4 + 49);

    // Coefficients for complex indices 4p .. 4p+3
    float2 fA0 = sf[0][4 * p],     fA1 = sf[0][4 * p + 1];
    float2 fA2 = sf[0][4 * p + 2], fA3 = sf[0][4 * p + 3];
    float2 fB0 = sf[1][4 * p],     fB1 = sf[1][4 * p + 1];
    float2 fB2 = sf[1][4 * p + 2], fB3 = sf[1][4 * p + 3];
    float2 fC0 = sf[2][4 * p],     fC1 = sf[2][4 * p + 1];
    float2 fC2 = sf[2][4 * p + 2], fC3 = sf[2][4 * p + 3];

    float4 accA, accB;
    accA.x = a3.x; accA.y = a3.y; accA.z = a3.z; accA.w = a3.w;
    accB.x = b3.x; accB.y = b3.y; accB.z = b3.z; accB.w = b3.w;

    // layer 0
    accA.x += a0.x * fA0.x - a0.y * fA0.y;  accA.y += a0.x * fA0.y + a0.y * fA0.x;
    accA.z += a0.z * fA1.x - a0.w * fA1.y;  accA.w += a0.z * fA1.y + a0.w * fA1.x;
    accB.x += b0.x * fA2.x - b0.y * fA2.y;  accB.y += b0.x * fA2.y + b0.y * fA2.x;
    accB.z += b0.z * fA3.x - b0.w * fA3.y;  accB.w += b0.z * fA3.y + b0.w * fA3.x;
    // layer 1
    accA.x += a1.x * fB0.x - a1.y * fB0.y;  accA.y += a1.x * fB0.y + a1.y * fB0.x;
    accA.z += a1.z * fB1.x - a1.w * fB1.y;  accA.w += a1.z * fB1.y + a1.w * fB1.x;
    accB.x += b1.x * fB2.x - b1.y * fB2.y;  accB.y += b1.x * fB2.y + b1.y * fB2.x;
    accB.z += b1.z * fB3.x - b1.w * fB3.y;  accB.w += b1.z * fB3.y + b1.w * fB3.x;
    // layer 2
    accA.x += a2.x * fC0.x - a2.y * fC0.y;  accA.y += a2.x * fC0.y + a2.y * fC0.x;
    accA.z += a2.z * fC1.x - a2.w * fC1.y;  accA.w += a2.z * fC1.y + a2.w * fC1.x;
    accB.x += b2.x * fC2.x - b2.y * fC2.y;  accB.y += b2.x * fC2.y + b2.y * fC2.x;
    accB.z += b2.z * fC3.x - b2.w * fC3.y;  accB.w += b2.z * fC3.y + b2.w * fC3.x;

    accA.x *= 0.25f; accA.y *= 0.25f; accA.z *= 0.25f; accA.w *= 0.25f;
    accB.x *= 0.25f; accB.y *= 0.25f; accB.z *= 0.25f; accB.w *= 0.25f;

    float4* o4 = (float4*)out + (long long)n * 16 + 2 * p;
    __stcs(o4 + 0, accA);
    __stcs(o4 + 1, accB);
}

extern "C" void kernel_launch(void* const* d_in, const int* in_sizes, int n_in,
                              void* d_out, int out_size)
{
    const float* feat  = (const float*)d_in[0];   // (N, 4, 64) fp32
    const float* r_vec = (const float*)d_in[1];   // (4, 32, 2) fp32
    float* out = (float*)d_out;                   // (N, 64) fp32

    const int N = in_sizes[0] / 256;              // 4*64 floats per row
    const long long total_pairs = (long long)N * 8;
    const int threads = 256;
    const int blocks = (int)((total_pairs + threads - 1) / threads);

    rotation_agg_kernel<<<blocks, threads>>>(feat, r_vec, out, total_pairs);
}

// round 4
// speedup vs baseline: 1.0093x; 1.0093x over previous
#include <cuda_runtime.h>

// Rotation_agg: out[n, :] = mean_l ( cmul(feat[n,l,:], finals[l,:]) ), finals[3]=identity.
// HBM-bound stream: 1.024 GB read + 256 MB write.
// R1 (1 float4/thread, coalesced) hit 90.9% DRAM / 178.7us. R2's 2-wide tile broke
// per-instruction coalescing (L1 wavefronts doubled) -> reverted. R3 = R1 + evict-first
// streaming cache hints only.

#define ROT_EPS 1e-12f

__global__ __launch_bounds__(256) void rotation_agg_kernel(
    const float* __restrict__ feat,
    const float* __restrict__ r_vec,
    float* __restrict__ out,
    int N)
{
    __shared__ float2 sf[3][32];   // finals for l=0,1,2 per complex index k

    const int tid = threadIdx.x;
    if (tid < 32) {
        const int k = tid;
        float2 rn[3];
#pragma unroll
        for (int e = 0; e < 3; e++) {
            float x = r_vec[e * 64 + k * 2 + 0];
            float y = r_vec[e * 64 + k * 2 + 1];
            float nrm = sqrtf(x * x + y * y);
            float inv = 1.0f / fmaxf(nrm, ROT_EPS);
            rn[e] = make_float2(x * inv, y * inv);
        }
        float2 f2 = make_float2(rn[2].x, -rn[2].y);               // conj(rn2)
        float2 c1 = make_float2(rn[1].x, -rn[1].y);               // conj(rn1)
        float2 f1 = make_float2(f2.x * c1.x - f2.y * c1.y,
                                f2.x * c1.y + f2.y * c1.x);       // f2 * conj(rn1)
        float2 f0 = make_float2(f1.x * rn[0].x - f1.y * rn[0].y,
                                f1.x * rn[0].y + f1.y * rn[0].x); // f1 * rn0
        sf[0][k] = f0;
        sf[1][k] = f1;
        sf[2][k] = f2;
    }
    __syncthreads();

    const long long t = (long long)blockIdx.x * blockDim.x + tid;
    const long long total = (long long)N * 16;   // 16 float4 columns per row
    if (t >= total) return;

    const int n = (int)(t >> 4);
    const int c = (int)(t & 15);                 // float4 column -> complex pairs 2c, 2c+1

    const float4* in4 = (const float4*)feat + (long long)n * 64 + c;  // 64 float4 per n

    // Batch all 4 layer loads up front (MLP=4); evict-first streaming policy.
    float4 v0 = __ldcs(in4 + 0);
    float4 v1 = __ldcs(in4 + 16);
    float4 v2 = __ldcs(in4 + 32);
    float4 v3 = __ldcs(in4 + 48);

    float2 f00 = sf[0][2 * c], f01 = sf[0][2 * c + 1];
    float2 f10 = sf[1][2 * c], f11 = sf[1][2 * c + 1];
    float2 f20 = sf[2][2 * c], f21 = sf[2][2 * c + 1];

    float4 acc;
    acc.x = v3.x; acc.y = v3.y; acc.z = v3.z; acc.w = v3.w;

    // l = 0
    acc.x += v0.x * f00.x - v0.y * f00.y;
    acc.y += v0.x * f00.y + v0.y * f00.x;
    acc.z += v0.z * f01.x - v0.w * f01.y;
    acc.w += v0.z * f01.y + v0.w * f01.x;
    // l = 1
    acc.x += v1.x * f10.x - v1.y * f10.y;
    acc.y += v1.x * f10.y + v1.y * f10.x;
    acc.z += v1.z * f11.x - v1.w * f11.y;
    acc.w += v1.z * f11.y + v1.w * f11.x;
    // l = 2
    acc.x += v2.x * f20.x - v2.y * f20.y;
    acc.y += v2.x * f20.y + v2.y * f20.x;
    acc.z += v2.z * f21.x - v2.w * f21.y;
    acc.w += v2.z * f21.y + v2.w * f21.x;

    acc.x *= 0.25f; acc.y *= 0.25f; acc.z *= 0.25f; acc.w *= 0.25f;

    __stcs((float4*)out + (long long)n * 16 + c, acc);
}

extern "C" void kernel_launch(void* const* d_in, const int* in_sizes, int n_in,
                              void* d_out, int out_size)
{
    const float* feat  = (const float*)d_in[0];   // (N, 4, 64) fp32
    const float* r_vec = (const float*)d_in[1];   // (4, 32, 2) fp32
    float* out = (float*)d_out;                   // (N, 64) fp32

    const int N = in_sizes[0] / 256;              // 4*64 floats per row
    const long long total = (long long)N * 16;
    const int threads = 256;
    const int blocks = (int)((total + threads - 1) / threads);

    rotation_agg_kernel<<<blocks, threads>>>(feat, r_vec, out, N);
}